// round 6
// baseline (speedup 1.0000x reference)
#include <cuda_runtime.h>
#include <cstdint>

// TurboQuantValue: per-row (128 elems) 4-bit min/max quantize + dequantize.
// out[i] = clip(rint((x[i]-vmin)/(vscale+1e-10)),0,15)*vscale + vmin
//
// One warp = 2 rows. Each thread owns 8 contiguous floats (32B) via a single
// 256-bit LDG/STG (sm_100+). Row r maps to half-warp r: lanes 0-15 -> row0,
// lanes 16-31 -> row1. Min/max via split-mask REDUX.SYNC (2 redux/warp).
// Streaming (.cs) hints: one-pass 512MB stream.

#define WARPS_PER_BLOCK 8
#define THREADS (WARPS_PER_BLOCK * 32)

// Order-preserving float<->uint key: key ascending <=> float ascending.
__device__ __forceinline__ unsigned f2key(float f) {
    unsigned u = __float_as_uint(f);
    return u ^ ((unsigned)((int)u >> 31) | 0x80000000u);
}
__device__ __forceinline__ float key2f(unsigned k) {
    unsigned u = (k & 0x80000000u) ? (k ^ 0x80000000u) : ~k;
    return __uint_as_float(u);
}

__global__ __launch_bounds__(THREADS, 8)
void turboquant_kernel(const float* __restrict__ in,
                       float* __restrict__ out,
                       int n_groups)   // groups of 2 rows (256 floats)
{
    int wid  = threadIdx.x >> 5;
    int lane = threadIdx.x & 31;
    int g = blockIdx.x * WARPS_PER_BLOCK + wid;
    if (g >= n_groups) return;

    // thread owns 8 contiguous floats; half-warp owns one 128-elem row
    const float* p = in + (size_t)g * 256 + (size_t)lane * 8;

    float v0, v1, v2, v3, v4, v5, v6, v7;
    asm volatile("ld.global.cs.v8.f32 {%0,%1,%2,%3,%4,%5,%6,%7}, [%8];"
                 : "=f"(v0), "=f"(v1), "=f"(v2), "=f"(v3),
                   "=f"(v4), "=f"(v5), "=f"(v6), "=f"(v7)
                 : "l"(p));

    // local min/max over 8 elements (3-level tree)
    float mn01 = fminf(v0, v1), mn23 = fminf(v2, v3);
    float mn45 = fminf(v4, v5), mn67 = fminf(v6, v7);
    float mx01 = fmaxf(v0, v1), mx23 = fmaxf(v2, v3);
    float mx45 = fmaxf(v4, v5), mx67 = fmaxf(v6, v7);
    float mn = fminf(fminf(mn01, mn23), fminf(mn45, mn67));
    float mx = fmaxf(fmaxf(mx01, mx23), fmaxf(mx45, mx67));

    // half-warp reduction: each 16-lane group reduces its own row
    unsigned mask = (lane & 16) ? 0xFFFF0000u : 0x0000FFFFu;
    float vmin = key2f(__reduce_min_sync(mask, f2key(mn)));
    float vmax = key2f(__reduce_max_sync(mask, f2key(mx)));

    float vscale = (vmax - vmin) / (15.0f + 1e-10f);
    float inv    = 1.0f / (vscale + 1e-10f);   // one IEEE div per thread
    float nb     = -vmin * inv;

    float q;
    q = fminf(fmaxf(rintf(fmaf(v0, inv, nb)), 0.0f), 15.0f);
    v0 = fmaf(q, vscale, vmin);
    q = fminf(fmaxf(rintf(fmaf(v1, inv, nb)), 0.0f), 15.0f);
    v1 = fmaf(q, vscale, vmin);
    q = fminf(fmaxf(rintf(fmaf(v2, inv, nb)), 0.0f), 15.0f);
    v2 = fmaf(q, vscale, vmin);
    q = fminf(fmaxf(rintf(fmaf(v3, inv, nb)), 0.0f), 15.0f);
    v3 = fmaf(q, vscale, vmin);
    q = fminf(fmaxf(rintf(fmaf(v4, inv, nb)), 0.0f), 15.0f);
    v4 = fmaf(q, vscale, vmin);
    q = fminf(fmaxf(rintf(fmaf(v5, inv, nb)), 0.0f), 15.0f);
    v5 = fmaf(q, vscale, vmin);
    q = fminf(fmaxf(rintf(fmaf(v6, inv, nb)), 0.0f), 15.0f);
    v6 = fmaf(q, vscale, vmin);
    q = fminf(fmaxf(rintf(fmaf(v7, inv, nb)), 0.0f), 15.0f);
    v7 = fmaf(q, vscale, vmin);

    float* o = out + (size_t)g * 256 + (size_t)lane * 8;
    asm volatile("st.global.cs.v8.f32 [%0], {%1,%2,%3,%4,%5,%6,%7,%8};"
                 :: "l"(o),
                    "f"(v0), "f"(v1), "f"(v2), "f"(v3),
                    "f"(v4), "f"(v5), "f"(v6), "f"(v7)
                 : "memory");
}

extern "C" void kernel_launch(void* const* d_in, const int* in_sizes, int n_in,
                              void* d_out, int out_size)
{
    const float* x = (const float*)d_in[0];
    float* out = (float*)d_out;

    int n_elems = in_sizes[0];          // 67,108,864
    int n_groups = n_elems / 256;       // 262,144 (2 rows per group)

    int blocks = (n_groups + WARPS_PER_BLOCK - 1) / WARPS_PER_BLOCK;
    turboquant_kernel<<<blocks, THREADS>>>(x, out, n_groups);
}

// round 8
// speedup vs baseline: 1.0066x; 1.0066x over previous
#include <cuda_runtime.h>
#include <cstdint>

// TurboQuantValue: per-row (128 elems) 4-bit min/max quantize + dequantize.
// out[i] = clip(rint((x[i]-vmin)/(vscale+1e-10)),0,15)*vscale + vmin
// vscale = (vmax-vmin)/(15+1e-10)
//
// Best-measured structure (R2/R5): one warp = TWO rows, float4 per thread,
// regs<=32, high occupancy, .cs streaming hints.
// Min/max via PAIRED integer REDUX (s32+u32), no monotone-key transforms:
//   float-min = fminf(asfloat(smin), asfloat(umax))   [no-NaN input]
//   float-max = fmaxf(asfloat(smax), asfloat(umin))

#define WARPS_PER_BLOCK 8
#define ROWS_PER_WARP 2
#define THREADS (WARPS_PER_BLOCK * 32)

__device__ __forceinline__ float4 quant_row(float4 a) {
    float mn = fminf(fminf(a.x, a.y), fminf(a.z, a.w));
    float mx = fmaxf(fmaxf(a.x, a.y), fmaxf(a.z, a.w));

    // warp min: s32-min handles all-positive case, u32-max handles any-negative
    unsigned bmn = __float_as_uint(mn);
    unsigned bmx = __float_as_uint(mx);
    float mn_s = __int_as_float(__reduce_min_sync(0xFFFFFFFFu, (int)bmn));
    float mn_u = __uint_as_float(__reduce_max_sync(0xFFFFFFFFu, bmn));
    float mx_s = __int_as_float(__reduce_max_sync(0xFFFFFFFFu, (int)bmx));
    float mx_u = __uint_as_float(__reduce_min_sync(0xFFFFFFFFu, bmx));
    mn = fminf(mn_s, mn_u);
    mx = fmaxf(mx_s, mx_u);

    float vscale = (mx - mn) / (15.0f + 1e-10f);
    float inv    = 1.0f / (vscale + 1e-10f);   // one IEEE div per row per lane
    float nb     = -mn * inv;

    float4 r;
    float q;
    q = fminf(fmaxf(rintf(fmaf(a.x, inv, nb)), 0.0f), 15.0f);
    r.x = fmaf(q, vscale, mn);
    q = fminf(fmaxf(rintf(fmaf(a.y, inv, nb)), 0.0f), 15.0f);
    r.y = fmaf(q, vscale, mn);
    q = fminf(fmaxf(rintf(fmaf(a.z, inv, nb)), 0.0f), 15.0f);
    r.z = fmaf(q, vscale, mn);
    q = fminf(fmaxf(rintf(fmaf(a.w, inv, nb)), 0.0f), 15.0f);
    r.w = fmaf(q, vscale, mn);
    return r;
}

__global__ __launch_bounds__(THREADS, 8)   // cap regs at 32 -> full occupancy
void turboquant_kernel(const float4* __restrict__ in,
                       float4* __restrict__ out,
                       int n_rows)
{
    int warp_in_block = threadIdx.x >> 5;
    int lane = threadIdx.x & 31;
    int row0 = (blockIdx.x * WARPS_PER_BLOCK + warp_in_block) * ROWS_PER_WARP;
    if (row0 >= n_rows) return;

    size_t idx0 = (size_t)row0 * 32 + lane;   // 32 float4 per row

    // front-load both rows (independent streaming LDG.128s, MLP=2)
    float4 a = __ldcs(&in[idx0]);
    float4 b = __ldcs(&in[idx0 + 32]);

    float4 ra = quant_row(a);
    float4 rb = quant_row(b);

    __stcs(&out[idx0],      ra);
    __stcs(&out[idx0 + 32], rb);
}

extern "C" void kernel_launch(void* const* d_in, const int* in_sizes, int n_in,
                              void* d_out, int out_size)
{
    const float4* x = (const float4*)d_in[0];
    float4* out = (float4*)d_out;

    int n_elems = in_sizes[0];          // 67,108,864
    int n_rows = n_elems / 128;         // 524,288

    int rows_per_block = WARPS_PER_BLOCK * ROWS_PER_WARP;
    int blocks = (n_rows + rows_per_block - 1) / rows_per_block;
    turboquant_kernel<<<blocks, THREADS>>>(x, out, n_rows);
}